// round 1
// baseline (speedup 1.0000x reference)
#include <cuda_runtime.h>

#define ROWS_REAL 9800          // 2 * 70 * 70 padded-grid rows
#define ROWS_PAD  9856          // 154 * 64 (GEMM M-tile multiple)
#define CIN       256
#define NOUT      768           // q | kf | vf packed

// ---------------- scratch (static device globals; no allocation) ----------------
__device__ float g_xp[ROWS_PAD * CIN];     // padded input, zero rows beyond 9800
__device__ float g_wcat[CIN * NOUT];       // [wq | wk | wv]
__device__ float g_C[ROWS_PAD * NOUT];     // [q | kf | vf] per padded-grid row

// ---------------- helpers ----------------
__device__ __forceinline__ int reflect64(int i) {
    if (i < 0) i = -i - 1;          // symmetric pad, left
    if (i > 63) i = 127 - i;        // symmetric pad, right
    return i;
}

__device__ __forceinline__ unsigned long long pk2(float x, float y) {
    unsigned long long r;
    asm("mov.b64 %0, {%1, %2};" : "=l"(r) : "f"(x), "f"(y));
    return r;
}
__device__ __forceinline__ void fma2(unsigned long long& d, unsigned long long a, unsigned long long b) {
    asm("fma.rn.f32x2 %0, %1, %2, %0;" : "+l"(d) : "l"(a), "l"(b));
}
__device__ __forceinline__ float2 upk2(unsigned long long v) {
    float2 f;
    asm("mov.b64 {%0, %1}, %2;" : "=f"(f.x), "=f"(f.y) : "l"(v));
    return f;
}

// ---------------- prep: padded input gather (float4) ----------------
__global__ void prep_xp_kernel(const float* __restrict__ x) {
    int idx = blockIdx.x * blockDim.x + threadIdx.x;   // over ROWS_PAD * 64 float4s
    if (idx >= ROWS_PAD * 64) return;
    int r  = idx >> 6;
    int c4 = (idx & 63) << 2;
    float4 v;
    if (r < ROWS_REAL) {
        int b   = r / 4900;
        int rem = r - b * 4900;
        int hp  = rem / 70;
        int wp  = rem - hp * 70;
        int hs  = reflect64(hp - 3);
        int ws  = reflect64(wp - 3);
        v = *(const float4*)(x + ((((b << 6) + hs) << 6) + ws) * 256 + c4);
    } else {
        v = make_float4(0.f, 0.f, 0.f, 0.f);
    }
    *(float4*)(g_xp + r * 256 + c4) = v;
}

// ---------------- prep: pack weights [256, 768] ----------------
__global__ void prep_w_kernel(const float* __restrict__ wq,
                              const float* __restrict__ wk,
                              const float* __restrict__ wv) {
    int idx = blockIdx.x * blockDim.x + threadIdx.x;
    if (idx >= CIN * NOUT) return;
    int r = idx / 768;
    int c = idx - r * 768;
    int sel = c >> 8;
    int cc  = c & 255;
    const float* w = (sel == 0) ? wq : (sel == 1 ? wk : wv);
    g_wcat[idx] = w[r * 256 + cc];
}

// ---------------- SGEMM: C[9856,768] = xp[9856,256] * Wcat[256,768] ----------------
// BM=64, BN=128, BK=16, 256 threads, TM=4, TN=8 via f32x2 packed FMA.
__global__ __launch_bounds__(256) void sgemm_kernel() {
    __shared__ float As[64][16];     // [m][k] — scalar broadcast reads
    __shared__ float Bs[16][128];    // [k][n]

    int tid  = threadIdx.x;
    int col0 = blockIdx.x * 128;
    int row0 = blockIdx.y * 64;
    int tx = tid & 15;   // n sub-tile (8 cols)
    int ty = tid >> 4;   // m sub-tile (4 rows)

    unsigned long long acc[4][4];
#pragma unroll
    for (int i = 0; i < 4; i++)
#pragma unroll
        for (int j = 0; j < 4; j++) acc[i][j] = 0ULL;

    int a_m  = tid >> 2;          // 0..63
    int a_k4 = (tid & 3) << 2;    // 0,4,8,12
    int kb   = tid >> 5;          // 0..7
    int nb   = (tid & 31) << 2;   // 0..124

    for (int k0 = 0; k0 < 256; k0 += 16) {
        *(float4*)(&As[a_m][a_k4]) =
            *(const float4*)(g_xp + (row0 + a_m) * 256 + k0 + a_k4);
        *(float4*)(&Bs[kb][nb]) =
            *(const float4*)(g_wcat + (k0 + kb) * 768 + col0 + nb);
        *(float4*)(&Bs[kb + 8][nb]) =
            *(const float4*)(g_wcat + (k0 + kb + 8) * 768 + col0 + nb);
        __syncthreads();

#pragma unroll
        for (int kk = 0; kk < 16; kk++) {
            float a0 = As[ty * 4 + 0][kk];
            float a1 = As[ty * 4 + 1][kk];
            float a2 = As[ty * 4 + 2][kk];
            float a3 = As[ty * 4 + 3][kk];
            float4 b0 = *(const float4*)(&Bs[kk][tx * 8]);
            float4 b1 = *(const float4*)(&Bs[kk][tx * 8 + 4]);
            unsigned long long bp0 = pk2(b0.x, b0.y);
            unsigned long long bp1 = pk2(b0.z, b0.w);
            unsigned long long bp2 = pk2(b1.x, b1.y);
            unsigned long long bp3 = pk2(b1.z, b1.w);
            unsigned long long ad;
            ad = pk2(a0, a0);
            fma2(acc[0][0], ad, bp0); fma2(acc[0][1], ad, bp1);
            fma2(acc[0][2], ad, bp2); fma2(acc[0][3], ad, bp3);
            ad = pk2(a1, a1);
            fma2(acc[1][0], ad, bp0); fma2(acc[1][1], ad, bp1);
            fma2(acc[1][2], ad, bp2); fma2(acc[1][3], ad, bp3);
            ad = pk2(a2, a2);
            fma2(acc[2][0], ad, bp0); fma2(acc[2][1], ad, bp1);
            fma2(acc[2][2], ad, bp2); fma2(acc[2][3], ad, bp3);
            ad = pk2(a3, a3);
            fma2(acc[3][0], ad, bp0); fma2(acc[3][1], ad, bp1);
            fma2(acc[3][2], ad, bp2); fma2(acc[3][3], ad, bp3);
        }
        __syncthreads();
    }

#pragma unroll
    for (int i = 0; i < 4; i++) {
        int row = row0 + ty * 4 + i;
        float* cp = g_C + row * 768 + col0 + tx * 8;
#pragma unroll
        for (int j = 0; j < 4; j++) {
            float2 f = upk2(acc[i][j]);
            *(float2*)(cp + j * 2) = f;
        }
    }
}

// ---------------- attention: one block per spatial position ----------------
// Block stages the 49 (kh,kw) sub-blocks of K and V (bias fused) into smem,
// then thread t (= output channel) reads its contiguous 49-tap window at
// offset t*49 (stride 49 mod 32 = 17 -> bank-conflict-free).
__global__ __launch_bounds__(256) void attn_kernel(const float* __restrict__ rh,
                                                   const float* __restrict__ rw,
                                                   float* __restrict__ out) {
    extern __shared__ float sm[];
    float* Ks = sm;            // 12544 floats
    float* Vs = sm + 12544;    // 12544 floats
    __shared__ int s_row[49];
    __shared__ int s_tap[49];

    int t = threadIdx.x;
    int s = blockIdx.x;                 // ((b*64 + h)*64 + w)
    int w = s & 63;
    int h = (s >> 6) & 63;
    int b = s >> 12;

    if (t < 49) {
        int kw = t % 7, kh = t / 7;
        s_row[t] = (b * 70 + h + kh) * 70 + (w + kw);
        s_tap[t] = (kh << 8) | kw;
    }
    __syncthreads();

#pragma unroll 7
    for (int sb = 0; sb < 49; sb++) {
        const float* base = g_C + s_row[sb] * 768;
        int tap = s_tap[sb];
        int kh = tap >> 8, kw = tap & 255;
        float bias = (t < 128) ? rh[kh * 128 + t] : rw[kw * 128 + (t - 128)];
        Ks[sb * 256 + t] = __ldg(base + 256 + t);
        Vs[sb * 256 + t] = __ldg(base + 512 + t) + bias;
    }
    __syncthreads();

    float q = g_C[((b * 70 + h + 3) * 70 + (w + 3)) * 768 + t];
    const float* kp = Ks + t * 49;
    const float* vp = Vs + t * 49;
    float ssum = 0.f, acc = 0.f;
#pragma unroll
    for (int j = 0; j < 49; j++) {
        float e = __expf(q * kp[j]);
        ssum += e;
        acc  += e * vp[j];
    }
    out[s * 256 + t] = acc / ssum;
}

// ---------------- launch ----------------
extern "C" void kernel_launch(void* const* d_in, const int* in_sizes, int n_in,
                              void* d_out, int out_size) {
    const float* x  = (const float*)d_in[0];
    const float* wq = (const float*)d_in[1];
    const float* wk = (const float*)d_in[2];
    const float* wv = (const float*)d_in[3];
    const float* rh = (const float*)d_in[4];
    const float* rw = (const float*)d_in[5];
    float* out = (float*)d_out;

    prep_xp_kernel<<<(ROWS_PAD * 64 + 255) / 256, 256>>>(x);
    prep_w_kernel<<<(CIN * NOUT + 255) / 256, 256>>>(wq, wk, wv);

    dim3 ggrid(6, 154);   // 768/128 N-tiles, 9856/64 M-tiles
    sgemm_kernel<<<ggrid, 256>>>();

    cudaFuncSetAttribute(attn_kernel,
                         cudaFuncAttributeMaxDynamicSharedMemorySize, 100352);
    attn_kernel<<<8192, 256, 100352>>>(rh, rw, out);
}

// round 2
// speedup vs baseline: 1.6060x; 1.6060x over previous
#include <cuda_runtime.h>

#define ROWS_REAL 9800          // 2 * 70 * 70 padded-grid rows
#define ROWS_PAD  9856          // 154 * 64 (GEMM M-tile multiple)
#define CIN       256
#define NOUT      768           // q | kf | vf packed

// ---------------- scratch (static device globals; no allocation) ----------------
__device__ float g_xp[ROWS_PAD * CIN];     // padded input, zero rows beyond 9800
__device__ float g_wcat[CIN * NOUT];       // [wq | wk | wv]
__device__ float g_C[ROWS_PAD * NOUT];     // [q | kf | vf] per padded-grid row

// ---------------- helpers ----------------
__device__ __forceinline__ int reflect64(int i) {
    if (i < 0) i = -i - 1;          // symmetric pad, left
    if (i > 63) i = 127 - i;        // symmetric pad, right
    return i;
}

__device__ __forceinline__ unsigned long long pk2(float x, float y) {
    unsigned long long r;
    asm("mov.b64 %0, {%1, %2};" : "=l"(r) : "f"(x), "f"(y));
    return r;
}
__device__ __forceinline__ void fma2(unsigned long long& d, unsigned long long a, unsigned long long b) {
    asm("fma.rn.f32x2 %0, %1, %2, %0;" : "+l"(d) : "l"(a), "l"(b));
}
__device__ __forceinline__ float2 upk2(unsigned long long v) {
    float2 f;
    asm("mov.b64 {%0, %1}, %2;" : "=f"(f.x), "=f"(f.y) : "l"(v));
    return f;
}

// ---------------- prep: padded input gather (float4) ----------------
__global__ void prep_xp_kernel(const float* __restrict__ x) {
    int idx = blockIdx.x * blockDim.x + threadIdx.x;   // over ROWS_PAD * 64 float4s
    if (idx >= ROWS_PAD * 64) return;
    int r  = idx >> 6;
    int c4 = (idx & 63) << 2;
    float4 v;
    if (r < ROWS_REAL) {
        int b   = r / 4900;
        int rem = r - b * 4900;
        int hp  = rem / 70;
        int wp  = rem - hp * 70;
        int hs  = reflect64(hp - 3);
        int ws  = reflect64(wp - 3);
        v = *(const float4*)(x + ((((b << 6) + hs) << 6) + ws) * 256 + c4);
    } else {
        v = make_float4(0.f, 0.f, 0.f, 0.f);
    }
    *(float4*)(g_xp + r * 256 + c4) = v;
}

// ---------------- prep: pack weights [256, 768] ----------------
__global__ void prep_w_kernel(const float* __restrict__ wq,
                              const float* __restrict__ wk,
                              const float* __restrict__ wv) {
    int idx = blockIdx.x * blockDim.x + threadIdx.x;
    if (idx >= CIN * NOUT) return;
    int r = idx / 768;
    int c = idx - r * 768;
    int sel = c >> 8;
    int cc  = c & 255;
    const float* w = (sel == 0) ? wq : (sel == 1 ? wk : wv);
    g_wcat[idx] = w[r * 256 + cc];
}

// ---------------- SGEMM: C[9856,768] = xp[9856,256] * Wcat[256,768] ----------------
// BM=64, BN=128, BK=16, 256 threads, TM=4, TN=8 via f32x2 packed FMA.
__global__ __launch_bounds__(256) void sgemm_kernel() {
    __shared__ float As[64][16];     // [m][k] — scalar broadcast reads
    __shared__ float Bs[16][128];    // [k][n]

    int tid  = threadIdx.x;
    int col0 = blockIdx.x * 128;
    int row0 = blockIdx.y * 64;
    int tx = tid & 15;   // n sub-tile (8 cols)
    int ty = tid >> 4;   // m sub-tile (4 rows)

    unsigned long long acc[4][4];
#pragma unroll
    for (int i = 0; i < 4; i++)
#pragma unroll
        for (int j = 0; j < 4; j++) acc[i][j] = 0ULL;

    int a_m  = tid >> 2;          // 0..63
    int a_k4 = (tid & 3) << 2;    // 0,4,8,12
    int kb   = tid >> 5;          // 0..7
    int nb   = (tid & 31) << 2;   // 0..124

    for (int k0 = 0; k0 < 256; k0 += 16) {
        *(float4*)(&As[a_m][a_k4]) =
            *(const float4*)(g_xp + (row0 + a_m) * 256 + k0 + a_k4);
        *(float4*)(&Bs[kb][nb]) =
            *(const float4*)(g_wcat + (k0 + kb) * 768 + col0 + nb);
        *(float4*)(&Bs[kb + 8][nb]) =
            *(const float4*)(g_wcat + (k0 + kb + 8) * 768 + col0 + nb);
        __syncthreads();

#pragma unroll
        for (int kk = 0; kk < 16; kk++) {
            float a0 = As[ty * 4 + 0][kk];
            float a1 = As[ty * 4 + 1][kk];
            float a2 = As[ty * 4 + 2][kk];
            float a3 = As[ty * 4 + 3][kk];
            float4 b0 = *(const float4*)(&Bs[kk][tx * 8]);
            float4 b1 = *(const float4*)(&Bs[kk][tx * 8 + 4]);
            unsigned long long bp0 = pk2(b0.x, b0.y);
            unsigned long long bp1 = pk2(b0.z, b0.w);
            unsigned long long bp2 = pk2(b1.x, b1.y);
            unsigned long long bp3 = pk2(b1.z, b1.w);
            unsigned long long ad;
            ad = pk2(a0, a0);
            fma2(acc[0][0], ad, bp0); fma2(acc[0][1], ad, bp1);
            fma2(acc[0][2], ad, bp2); fma2(acc[0][3], ad, bp3);
            ad = pk2(a1, a1);
            fma2(acc[1][0], ad, bp0); fma2(acc[1][1], ad, bp1);
            fma2(acc[1][2], ad, bp2); fma2(acc[1][3], ad, bp3);
            ad = pk2(a2, a2);
            fma2(acc[2][0], ad, bp0); fma2(acc[2][1], ad, bp1);
            fma2(acc[2][2], ad, bp2); fma2(acc[2][3], ad, bp3);
            ad = pk2(a3, a3);
            fma2(acc[3][0], ad, bp0); fma2(acc[3][1], ad, bp1);
            fma2(acc[3][2], ad, bp2); fma2(acc[3][3], ad, bp3);
        }
        __syncthreads();
    }

#pragma unroll
    for (int i = 0; i < 4; i++) {
        int row = row0 + ty * 4 + i;
        float* cp = g_C + row * 768 + col0 + tx * 8;
#pragma unroll
        for (int j = 0; j < 4; j++) {
            float2 f = upk2(acc[i][j]);
            *(float2*)(cp + j * 2) = f;
        }
    }
}

// ---------------- attention: one block per spatial position, phase-split K/V ----------------
// Flattened (tap,ch) block per position: element u = tap*256 + ch; out channel t
// consumes the contiguous window u in [t*49, t*49+49). Stage K -> e[49] in regs,
// overwrite smem with V(+bias), accumulate. smem 50 KB -> 3 blocks/SM.
__global__ __launch_bounds__(256, 3) void attn_kernel(const float* __restrict__ rh,
                                                      const float* __restrict__ rw,
                                                      float* __restrict__ out) {
    extern __shared__ float sm[];          // 12544 floats (49 taps x 256 ch)
    float4* sm4 = (float4*)sm;

    int t = threadIdx.x;
    int s = blockIdx.x;                    // ((b*64 + h)*64 + w)
    int w = s & 63;
    int h = (s >> 6) & 63;
    int b = s >> 12;
    int rowbase = (b * 70 + h) * 70 + w;   // padded-grid row of tap (0,0)

    const float4* C4  = (const float4*)g_C;
    const float4* rh4 = (const float4*)rh;
    const float4* rw4 = (const float4*)rw;

    // ---- stage K (3136 float4s), addresses fully register-computed ----
#pragma unroll
    for (int i = 0; i < 13; i++) {
        int idx = i * 256 + t;
        if (idx < 3136) {
            int sb  = idx >> 6;                 // tap 0..48
            int kh  = (sb * 37) >> 8;           // sb / 7 for sb < 49
            int kw  = sb - kh * 7;
            int ch4 = idx & 63;
            sm4[idx] = C4[(rowbase + kh * 70 + kw) * 192 + 64 + ch4];
        }
    }
    __syncthreads();

    // ---- e-phase: q * K window, exp into registers ----
    float q = g_C[(rowbase + 3 * 70 + 3) * 768 + t];
    float e[49];
    const float* kp = sm + t * 49;          // stride 49 across lanes: conflict-free
#pragma unroll
    for (int j = 0; j < 49; j++)
        e[j] = __expf(q * kp[j]);
    float s0 = 0.f, s1 = 0.f, s2 = 0.f, s3 = 0.f;
#pragma unroll
    for (int j = 0; j < 48; j += 4) { s0 += e[j]; s1 += e[j+1]; s2 += e[j+2]; s3 += e[j+3]; }
    float ssum = (s0 + s1) + (s2 + s3) + e[48];
    __syncthreads();                        // everyone done reading K

    // ---- stage V + bias (overwrite smem) ----
#pragma unroll
    for (int i = 0; i < 13; i++) {
        int idx = i * 256 + t;
        if (idx < 3136) {
            int sb  = idx >> 6;
            int kh  = (sb * 37) >> 8;
            int kw  = sb - kh * 7;
            int ch4 = idx & 63;
            float4 v  = C4[(rowbase + kh * 70 + kw) * 192 + 128 + ch4];
            float4 bb = (ch4 < 32) ? rh4[kh * 32 + ch4] : rw4[kw * 32 + (ch4 - 32)];
            v.x += bb.x; v.y += bb.y; v.z += bb.z; v.w += bb.w;
            sm4[idx] = v;
        }
    }
    __syncthreads();

    // ---- acc-phase ----
    const float* vp = sm + t * 49;
    float a0 = 0.f, a1 = 0.f, a2 = 0.f, a3 = 0.f;
#pragma unroll
    for (int j = 0; j < 48; j += 4) {
        a0 += e[j]   * vp[j];
        a1 += e[j+1] * vp[j+1];
        a2 += e[j+2] * vp[j+2];
        a3 += e[j+3] * vp[j+3];
    }
    float acc = (a0 + a1) + (a2 + a3) + e[48] * vp[48];
    out[s * 256 + t] = acc / ssum;
}

// ---------------- launch ----------------
extern "C" void kernel_launch(void* const* d_in, const int* in_sizes, int n_in,
                              void* d_out, int out_size) {
    const float* x  = (const float*)d_in[0];
    const float* wq = (const float*)d_in[1];
    const float* wk = (const float*)d_in[2];
    const float* wv = (const float*)d_in[3];
    const float* rh = (const float*)d_in[4];
    const float* rw = (const float*)d_in[5];
    float* out = (float*)d_out;

    prep_xp_kernel<<<(ROWS_PAD * 64 + 255) / 256, 256>>>(x);
    prep_w_kernel<<<(CIN * NOUT + 255) / 256, 256>>>(wq, wk, wv);

    dim3 ggrid(6, 154);   // 768/128 N-tiles, 9856/64 M-tiles
    sgemm_kernel<<<ggrid, 256>>>();

    cudaFuncSetAttribute(attn_kernel,
                         cudaFuncAttributeMaxDynamicSharedMemorySize, 50176);
    attn_kernel<<<8192, 256, 50176>>>(rh, rw, out);
}

// round 3
// speedup vs baseline: 1.9247x; 1.1984x over previous
#include <cuda_runtime.h>

#define ROWS_REAL 9800          // 2 * 70 * 70 padded-grid rows
#define ROWS_PAD  9856          // 154 * 64
#define CIN       256
#define NOUT      768           // q | kf | vf packed

__device__ float g_xp[ROWS_PAD * CIN];
__device__ float g_wcat[CIN * NOUT];
__device__ float g_C[ROWS_PAD * NOUT];

// ---------------- helpers ----------------
__device__ __forceinline__ int reflect64(int i) {
    if (i < 0) i = -i - 1;
    if (i > 63) i = 127 - i;
    return i;
}
__device__ __forceinline__ void fma2(unsigned long long& d, unsigned long long a, unsigned long long b) {
    asm("fma.rn.f32x2 %0, %1, %2, %0;" : "+l"(d) : "l"(a), "l"(b));
}
__device__ __forceinline__ float2 upk2(unsigned long long v) {
    float2 f;
    asm("mov.b64 {%0, %1}, %2;" : "=f"(f.x), "=f"(f.y) : "l"(v));
    return f;
}

// ---------------- prep: padded input gather ----------------
__global__ void prep_xp_kernel(const float* __restrict__ x) {
    int idx = blockIdx.x * blockDim.x + threadIdx.x;
    if (idx >= ROWS_PAD * 64) return;
    int r  = idx >> 6;
    int c4 = (idx & 63) << 2;
    float4 v;
    if (r < ROWS_REAL) {
        int b   = r / 4900;
        int rem = r - b * 4900;
        int hp  = rem / 70;
        int wp  = rem - hp * 70;
        int hs  = reflect64(hp - 3);
        int ws  = reflect64(wp - 3);
        v = *(const float4*)(x + ((((b << 6) + hs) << 6) + ws) * 256 + c4);
    } else {
        v = make_float4(0.f, 0.f, 0.f, 0.f);
    }
    *(float4*)(g_xp + r * 256 + c4) = v;
}

// ---------------- prep: pack weights [256, 768] ----------------
__global__ void prep_w_kernel(const float* __restrict__ wq,
                              const float* __restrict__ wk,
                              const float* __restrict__ wv) {
    int idx = blockIdx.x * blockDim.x + threadIdx.x;
    if (idx >= CIN * NOUT) return;
    int r = idx / 768;
    int c = idx - r * 768;
    int sel = c >> 8;
    int cc  = c & 255;
    const float* w = (sel == 0) ? wq : (sel == 1 ? wk : wv);
    g_wcat[idx] = w[r * 256 + cc];
}

// ---------------- SGEMM: C[9856,768] = xp * Wcat ----------------
// BM=128 BN=128 BK=16, 256 thr, TM=TN=8, A pre-duplicated float2, double buffer.
#define BM 128
#define BN 128
#define BK 16

__global__ __launch_bounds__(256, 2) void sgemm_kernel() {
    __shared__ float2 As[2][BK][BM];   // (a,a) packed: 32 KB
    __shared__ float  Bs[2][BK][BN];   // 16 KB

    int tid = threadIdx.x;
    int tx = tid & 15, ty = tid >> 4;
    int col0 = blockIdx.x * BN;
    int row0 = blockIdx.y * BM;

    int aRow = tid >> 1;              // 0..127
    int aC4  = (tid & 1) * 2;         // float4 idx 0 or 2 within 16-float k-slice
    int bRow = tid >> 4;              // 0..15
    int bC4  = (tid & 15) * 2;        // float4 idx within 128-float row

    const float4* Ag4 = (const float4*)g_xp + (row0 + aRow) * 64 + aC4;
    const float4* Bg4 = (const float4*)g_wcat + bRow * 192 + (col0 >> 2) + bC4;

    // preload tile 0
    float4 a0 = Ag4[0], a1 = Ag4[1];
    float4 b0 = Bg4[0], b1 = Bg4[1];
    {
        int kb = aC4 * 4;
        As[0][kb + 0][aRow] = make_float2(a0.x, a0.x);
        As[0][kb + 1][aRow] = make_float2(a0.y, a0.y);
        As[0][kb + 2][aRow] = make_float2(a0.z, a0.z);
        As[0][kb + 3][aRow] = make_float2(a0.w, a0.w);
        As[0][kb + 4][aRow] = make_float2(a1.x, a1.x);
        As[0][kb + 5][aRow] = make_float2(a1.y, a1.y);
        As[0][kb + 6][aRow] = make_float2(a1.z, a1.z);
        As[0][kb + 7][aRow] = make_float2(a1.w, a1.w);
        *(float4*)&Bs[0][bRow][bC4 * 4]     = b0;
        *(float4*)&Bs[0][bRow][bC4 * 4 + 4] = b1;
    }
    __syncthreads();

    unsigned long long acc[8][4];
#pragma unroll
    for (int i = 0; i < 8; i++)
#pragma unroll
        for (int j = 0; j < 4; j++) acc[i][j] = 0ULL;

    for (int kt = 0; kt < 16; kt++) {
        int buf = kt & 1;
        if (kt < 15) {
            a0 = Ag4[(kt + 1) * 4];
            a1 = Ag4[(kt + 1) * 4 + 1];
            b0 = Bg4[(kt + 1) * 3072];
            b1 = Bg4[(kt + 1) * 3072 + 1];
        }
#pragma unroll
        for (int kk = 0; kk < BK; kk++) {
            ulonglong2 a01 = *(const ulonglong2*)&As[buf][kk][ty * 8 + 0];
            ulonglong2 a23 = *(const ulonglong2*)&As[buf][kk][ty * 8 + 2];
            ulonglong2 a45 = *(const ulonglong2*)&As[buf][kk][ty * 8 + 4];
            ulonglong2 a67 = *(const ulonglong2*)&As[buf][kk][ty * 8 + 6];
            ulonglong2 bp01 = *(const ulonglong2*)&Bs[buf][kk][tx * 8];
            ulonglong2 bp23 = *(const ulonglong2*)&Bs[buf][kk][tx * 8 + 4];
            fma2(acc[0][0], a01.x, bp01.x); fma2(acc[0][1], a01.x, bp01.y);
            fma2(acc[0][2], a01.x, bp23.x); fma2(acc[0][3], a01.x, bp23.y);
            fma2(acc[1][0], a01.y, bp01.x); fma2(acc[1][1], a01.y, bp01.y);
            fma2(acc[1][2], a01.y, bp23.x); fma2(acc[1][3], a01.y, bp23.y);
            fma2(acc[2][0], a23.x, bp01.x); fma2(acc[2][1], a23.x, bp01.y);
            fma2(acc[2][2], a23.x, bp23.x); fma2(acc[2][3], a23.x, bp23.y);
            fma2(acc[3][0], a23.y, bp01.x); fma2(acc[3][1], a23.y, bp01.y);
            fma2(acc[3][2], a23.y, bp23.x); fma2(acc[3][3], a23.y, bp23.y);
            fma2(acc[4][0], a45.x, bp01.x); fma2(acc[4][1], a45.x, bp01.y);
            fma2(acc[4][2], a45.x, bp23.x); fma2(acc[4][3], a45.x, bp23.y);
            fma2(acc[5][0], a45.y, bp01.x); fma2(acc[5][1], a45.y, bp01.y);
            fma2(acc[5][2], a45.y, bp23.x); fma2(acc[5][3], a45.y, bp23.y);
            fma2(acc[6][0], a67.x, bp01.x); fma2(acc[6][1], a67.x, bp01.y);
            fma2(acc[6][2], a67.x, bp23.x); fma2(acc[6][3], a67.x, bp23.y);
            fma2(acc[7][0], a67.y, bp01.x); fma2(acc[7][1], a67.y, bp01.y);
            fma2(acc[7][2], a67.y, bp23.x); fma2(acc[7][3], a67.y, bp23.y);
        }
        if (kt < 15) {
            int nb = buf ^ 1;
            int kb = aC4 * 4;
            As[nb][kb + 0][aRow] = make_float2(a0.x, a0.x);
            As[nb][kb + 1][aRow] = make_float2(a0.y, a0.y);
            As[nb][kb + 2][aRow] = make_float2(a0.z, a0.z);
            As[nb][kb + 3][aRow] = make_float2(a0.w, a0.w);
            As[nb][kb + 4][aRow] = make_float2(a1.x, a1.x);
            As[nb][kb + 5][aRow] = make_float2(a1.y, a1.y);
            As[nb][kb + 6][aRow] = make_float2(a1.z, a1.z);
            As[nb][kb + 7][aRow] = make_float2(a1.w, a1.w);
            *(float4*)&Bs[nb][bRow][bC4 * 4]     = b0;
            *(float4*)&Bs[nb][bRow][bC4 * 4 + 4] = b1;
            __syncthreads();
        }
    }

#pragma unroll
    for (int i = 0; i < 8; i++) {
        float* cp = g_C + (row0 + ty * 8 + i) * 768 + col0 + tx * 8;
        float2 f0 = upk2(acc[i][0]);
        float2 f1 = upk2(acc[i][1]);
        float2 f2 = upk2(acc[i][2]);
        float2 f3 = upk2(acc[i][3]);
        *(float4*)cp       = make_float4(f0.x, f0.y, f1.x, f1.y);
        *(float4*)(cp + 4) = make_float4(f2.x, f2.y, f3.x, f3.y);
    }
}

// ---------------- attention: 2x2 spatial tile per block ----------------
// smem: 64 shared rows, interleaved [K row (256f) | V row (256f)] -> 32768 floats,
// then bias tables rh (896) + rw (896). Bias vector per window lives in registers.
__global__ __launch_bounds__(512, 1) void attn_kernel(const float* __restrict__ rh,
                                                      const float* __restrict__ rw,
                                                      float* __restrict__ out) {
    extern __shared__ float sm[];
    float* bias_h = sm + 32768;
    float* bias_w = bias_h + 896;

    int t = threadIdx.x;
    int bid = blockIdx.x;
    int w2 = bid & 31, h2 = (bid >> 5) & 31, b = bid >> 10;
    int h0 = h2 * 2, w0 = w2 * 2;

    const float4* C4 = (const float4*)g_C;
    float4* sm4 = (float4*)sm;

    // stage K+V tile: 8192 float4s (K: which=0, V: which=1), interleaved rows
#pragma unroll
    for (int i = 0; i < 16; i++) {
        int idx = i * 512 + t;
        int which = idx >> 12;           // 0=K, 1=V
        int rr = (idx >> 6) & 63;        // tile row 0..63 (rr8 = h off, rc = w off)
        int ch4 = idx & 63;
        int rr8 = rr >> 3, rc = rr & 7;
        int grow = (b * 70 + h0 + rr8) * 70 + (w0 + rc);
        sm4[rr * 128 + (which << 6) + ch4] = C4[grow * 192 + 64 + (which << 6) + ch4];
    }
    // stage bias tables
    if (t < 224)                ((float4*)bias_h)[t] = ((const float4*)rh)[t];
    else if (t < 448)           ((float4*)bias_w)[t - 224] = ((const float4*)rw)[t - 224];
    __syncthreads();

    int slot = t >> 8;
    int c = t & 255;
    int u0 = c * 49;
    int tap0 = u0 >> 8;
    int ch0 = u0 & 255;
    int kh0 = (tap0 * 37) >> 8;          // tap0 / 7 for tap0 < 49
    int kw0 = tap0 - kh0 * 7;

    // bias window into registers (position-independent)
    float breg[49];
    {
        int ch = ch0, kh = kh0, kw = kw0;
#pragma unroll
        for (int j = 0; j < 49; j++) {
            breg[j] = (ch < 128) ? bias_h[kh * 128 + ch] : bias_w[kw * 128 + (ch - 128)];
            if (++ch == 256) { ch = 0; if (++kw == 7) { kw = 0; ++kh; } }
        }
    }

#pragma unroll
    for (int p = 0; p < 2; p++) {
        int posid = slot * 2 + p;
        int dh = posid >> 1, dw = posid & 1;
        float q = g_C[((b * 70 + h0 + dh + 3) * 70 + (w0 + dw + 3)) * 768 + c];

        int ch = ch0, kh = kh0, kw = kw0;
        int ka = (((dh + kh0) << 3) + dw + kw0) * 512 + ch0;
        float ssum = 0.f, acc = 0.f;
#pragma unroll
        for (int j = 0; j < 49; j++) {
            float kv = sm[ka];
            float vv = sm[ka + 256];
            float e = __expf(q * kv);
            ssum += e;
            acc += e * (vv + breg[j]);
            ++ka;
            if (++ch == 256) {           // at most one wrap per window
                ch = 0;
                if (++kw == 7) { kw = 0; ++kh; }
                ka = (((dh + kh) << 3) + dw + kw) * 512;
            }
        }
        out[((b * 64 + h0 + dh) * 64 + (w0 + dw)) * 256 + c] = acc / ssum;
    }
}

// ---------------- launch ----------------
extern "C" void kernel_launch(void* const* d_in, const int* in_sizes, int n_in,
                              void* d_out, int out_size) {
    const float* x  = (const float*)d_in[0];
    const float* wq = (const float*)d_in[1];
    const float* wk = (const float*)d_in[2];
    const float* wv = (const float*)d_in[3];
    const float* rh = (const float*)d_in[4];
    const float* rw = (const float*)d_in[5];
    float* out = (float*)d_out;

    prep_xp_kernel<<<(ROWS_PAD * 64 + 255) / 256, 256>>>(x);
    prep_w_kernel<<<(CIN * NOUT + 255) / 256, 256>>>(wq, wk, wv);

    dim3 ggrid(6, 77);   // N tiles x M tiles
    sgemm_kernel<<<ggrid, 256>>>();

    cudaFuncSetAttribute(attn_kernel,
                         cudaFuncAttributeMaxDynamicSharedMemorySize, 138240);
    attn_kernel<<<2048, 512, 138240>>>(rh, rw, out);
}